// round 1
// baseline (speedup 1.0000x reference)
#include <cuda_runtime.h>
#include <cstdint>

#define D 128
#define NMAX 100000

// Scratch: hW = h @ W^T  (fp32, 51.2 MB) and CSR row pointers.
__device__ float g_hW[(size_t)NMAX * D];
__device__ int   g_rowptr[NMAX + 1];

// ---------------------------------------------------------------------------
// Kernel 1: hW[i][j] = sum_k h[i][k] * W[j][k]
// Block: 256 threads, computes a 64-row x 128-col tile.
// Each thread: 8 rows x 4 cols = 32 accumulators.
// ---------------------------------------------------------------------------
__global__ __launch_bounds__(256) void gemm_hwt_kernel(
    const float* __restrict__ h,
    const float* __restrict__ W,
    int N)
{
    __shared__ float Asm[64][32];      // h tile chunk    (rows x k)
    __shared__ float Wtsm[32][129];    // W^T chunk: Wtsm[k][j] = W[j][k0+k]

    const int t  = threadIdx.x;
    const int tx = t & 31;   // column lane (cols tx, tx+32, tx+64, tx+96)
    const int ty = t >> 5;   // row group (rows ty*8 .. ty*8+7) -- all lanes of a warp share ty
    const int m0 = blockIdx.x * 64;

    float acc[8][4];
#pragma unroll
    for (int r = 0; r < 8; r++)
#pragma unroll
        for (int c = 0; c < 4; c++) acc[r][c] = 0.f;

    for (int k0 = 0; k0 < D; k0 += 32) {
        // Load W chunk transposed: lanes vary kk -> coalesced gmem read,
        // smem store stride 129 floats -> conflict-free.
#pragma unroll
        for (int p = 0; p < 16; p++) {
            int j  = p * 8 + ty;
            int kk = tx;
            Wtsm[kk][j] = W[j * D + k0 + kk];
        }
        // Load h tile chunk: 64x32 floats, 8 per thread, coalesced.
#pragma unroll
        for (int i = 0; i < 8; i++) {
            int idx = t + i * 256;
            int row = idx >> 5;
            int kk  = idx & 31;
            int gr  = m0 + row;
            Asm[row][kk] = (gr < N) ? h[(size_t)gr * D + k0 + kk] : 0.f;
        }
        __syncthreads();

#pragma unroll
        for (int kk = 0; kk < 32; kk++) {
            float a[8], w[4];
#pragma unroll
            for (int r = 0; r < 8; r++) a[r] = Asm[ty * 8 + r][kk];   // warp-broadcast
#pragma unroll
            for (int c = 0; c < 4; c++) w[c] = Wtsm[kk][tx + 32 * c]; // conflict-free
#pragma unroll
            for (int r = 0; r < 8; r++)
#pragma unroll
                for (int c = 0; c < 4; c++)
                    acc[r][c] = fmaf(a[r], w[c], acc[r][c]);
        }
        __syncthreads();
    }

#pragma unroll
    for (int r = 0; r < 8; r++) {
        int row = m0 + ty * 8 + r;
        if (row < N) {
#pragma unroll
            for (int c = 0; c < 4; c++)
                g_hW[(size_t)row * D + tx + 32 * c] = acc[r][c];
        }
    }
}

// ---------------------------------------------------------------------------
// Kernel 2: build CSR row pointers from sorted edge_rows. O(E) scatter.
// g_rowptr[i] = first edge index with row >= i ; g_rowptr[N] = E.
// ---------------------------------------------------------------------------
__global__ __launch_bounds__(256) void build_rowptr_kernel(
    const int* __restrict__ rows, int E, int N)
{
    int e = blockIdx.x * blockDim.x + threadIdx.x;
    if (e >= E) return;
    int r     = rows[e];
    int rprev = (e == 0) ? -1 : rows[e - 1];
    for (int i = rprev + 1; i <= r; i++) g_rowptr[i] = e;
    if (e == E - 1) {
        for (int i = r + 1; i <= N; i++) g_rowptr[i] = E;
    }
}

// ---------------------------------------------------------------------------
// Kernel 3: SpMM + bias + ReLU. One warp per node.
// Lane l owns float4 #l of the 128-dim row (dims 4l..4l+3).
// Edges batched 32-per-warp, broadcast via shfl; each edge does one
// coalesced 512B gather of g_hW[col].
// ---------------------------------------------------------------------------
__global__ __launch_bounds__(256) void spmm_kernel(
    const int*   __restrict__ cols,
    const float* __restrict__ vals,
    const float* __restrict__ b,
    float*       __restrict__ out,
    int N)
{
    const int warp = (blockIdx.x * blockDim.x + threadIdx.x) >> 5;
    const int lane = threadIdx.x & 31;
    if (warp >= N) return;

    const int lo = g_rowptr[warp];
    const int hi = g_rowptr[warp + 1];

    const float4* __restrict__ hW4 = reinterpret_cast<const float4*>(g_hW);

    float4 acc = make_float4(0.f, 0.f, 0.f, 0.f);

    for (int e0 = lo; e0 < hi; e0 += 32) {
        const int n = min(32, hi - e0);
        int   c = 0;
        float v = 0.f;
        if (lane < n) {
            c = cols[e0 + lane];
            v = vals[e0 + lane];
        }
        int j = 0;
        // 2 edges per iteration for MLP
        for (; j + 1 < n; j += 2) {
            int   c0 = __shfl_sync(0xffffffffu, c, j);
            float v0 = __shfl_sync(0xffffffffu, v, j);
            int   c1 = __shfl_sync(0xffffffffu, c, j + 1);
            float v1 = __shfl_sync(0xffffffffu, v, j + 1);
            float4 x0 = hW4[(size_t)c0 * 32 + lane];
            float4 x1 = hW4[(size_t)c1 * 32 + lane];
            acc.x = fmaf(v0, x0.x, acc.x);
            acc.y = fmaf(v0, x0.y, acc.y);
            acc.z = fmaf(v0, x0.z, acc.z);
            acc.w = fmaf(v0, x0.w, acc.w);
            acc.x = fmaf(v1, x1.x, acc.x);
            acc.y = fmaf(v1, x1.y, acc.y);
            acc.z = fmaf(v1, x1.z, acc.z);
            acc.w = fmaf(v1, x1.w, acc.w);
        }
        if (j < n) {
            int   c0 = __shfl_sync(0xffffffffu, c, j);
            float v0 = __shfl_sync(0xffffffffu, v, j);
            float4 x0 = hW4[(size_t)c0 * 32 + lane];
            acc.x = fmaf(v0, x0.x, acc.x);
            acc.y = fmaf(v0, x0.y, acc.y);
            acc.z = fmaf(v0, x0.z, acc.z);
            acc.w = fmaf(v0, x0.w, acc.w);
        }
    }

    const float4 bb = reinterpret_cast<const float4*>(b)[lane];
    float4 o;
    o.x = fmaxf(acc.x + bb.x, 0.f);
    o.y = fmaxf(acc.y + bb.y, 0.f);
    o.z = fmaxf(acc.z + bb.z, 0.f);
    o.w = fmaxf(acc.w + bb.w, 0.f);
    reinterpret_cast<float4*>(out)[(size_t)warp * 32 + lane] = o;
}

// ---------------------------------------------------------------------------
// Launch: gemm (hW) -> rowptr -> spmm, all on the capture stream.
// Inputs (metadata order): edge_rows i32, edge_cols i32, edge_vals f32,
//                          h f32 [N,128], W f32 [128,128], b f32 [128]
// ---------------------------------------------------------------------------
extern "C" void kernel_launch(void* const* d_in, const int* in_sizes, int n_in,
                              void* d_out, int out_size)
{
    const int*   rows = (const int*)  d_in[0];
    const int*   cols = (const int*)  d_in[1];
    const float* vals = (const float*)d_in[2];
    const float* h    = (const float*)d_in[3];
    const float* W    = (const float*)d_in[4];
    const float* b    = (const float*)d_in[5];
    float*       out  = (float*)d_out;

    const int E = in_sizes[0];
    const int N = in_sizes[3] / D;   // 100000

    gemm_hwt_kernel<<<(N + 63) / 64, 256>>>(h, W, N);
    build_rowptr_kernel<<<(E + 255) / 256, 256>>>(rows, E, N);
    spmm_kernel<<<(N + 7) / 8, 256>>>(cols, vals, b, out, N);
}

// round 2
// speedup vs baseline: 1.6590x; 1.6590x over previous
#include <cuda_runtime.h>
#include <cuda_fp16.h>
#include <cstdint>

#define D 128
#define NMAX 100000

// Scratch (device globals -- no allocation allowed):
__device__ __half g_Wh[D * D];                 // W in fp16, [j][k] row-major
__device__ __half g_hWh[(size_t)NMAX * D];     // hW = h @ W^T in fp16
__device__ int    g_rowptr[NMAX + 1];

// ---------------------------------------------------------------------------
// Kernel 0: convert W fp32 -> fp16
// ---------------------------------------------------------------------------
__global__ void convert_w_kernel(const float* __restrict__ W)
{
    int i = blockIdx.x * blockDim.x + threadIdx.x;
    if (i < D * D) g_Wh[i] = __float2half(W[i]);
}

// ---------------------------------------------------------------------------
// Kernel 1: hW[i][j] = sum_k h[i][k] * W[j][k] via mma.sync m16n8k16 fp16.
// Block: 256 threads (8 warps). Tile: 128 rows x 128 cols, K chunked by 64.
// Warp w computes rows 16w..16w+15, all 128 cols (16 n-tiles of 8).
// ---------------------------------------------------------------------------
#define KC 64          // K chunk
#define KPAD 72        // chunk + 8-half pad (conflict-free ldmatrix-less LDS)

__device__ __forceinline__ void mma16816(float4& c,
                                         uint32_t a0, uint32_t a1, uint32_t a2, uint32_t a3,
                                         uint32_t b0, uint32_t b1)
{
    asm volatile(
        "mma.sync.aligned.m16n8k16.row.col.f32.f16.f16.f32 "
        "{%0,%1,%2,%3}, {%4,%5,%6,%7}, {%8,%9}, {%0,%1,%2,%3};\n"
        : "+f"(c.x), "+f"(c.y), "+f"(c.z), "+f"(c.w)
        : "r"(a0), "r"(a1), "r"(a2), "r"(a3), "r"(b0), "r"(b1));
}

__global__ __launch_bounds__(256) void gemm_hwt_fp16_kernel(
    const float* __restrict__ h, int N)
{
    __shared__ __half Asm[128][KPAD];   // h tile chunk (fp16)
    __shared__ __half Bsm[128][KPAD];   // W chunk: Bsm[j][kk] = W[j][kc*64+kk]

    const int t    = threadIdx.x;
    const int lane = t & 31;
    const int warp = t >> 5;
    const int m0   = blockIdx.x * 128;

    const int qr = lane >> 2;        // 0..7  (row within 8-group)
    const int qc = (lane & 3) * 2;   // 0,2,4,6 (col pair)
    const int mrow = warp * 16 + qr;

    float4 acc[16];
#pragma unroll
    for (int j = 0; j < 16; j++) acc[j] = make_float4(0.f, 0.f, 0.f, 0.f);

    for (int kc = 0; kc < 2; kc++) {
        // ---- load A chunk: 128 rows x 64 k, fp32 -> fp16, guarded ----
        // 2048 float4 loads, 8 per thread
#pragma unroll
        for (int it = 0; it < 8; it++) {
            int idx = t + it * 256;          // 0..2047
            int row = idx >> 4;              // /16
            int q   = idx & 15;              // float4 index within 64 k
            int gr  = m0 + row;
            float4 v = make_float4(0.f, 0.f, 0.f, 0.f);
            if (gr < N)
                v = reinterpret_cast<const float4*>(h + (size_t)gr * D + kc * KC)[q];
            __half2 lo = __floats2half2_rn(v.x, v.y);
            __half2 hi = __floats2half2_rn(v.z, v.w);
            __half2* dst = reinterpret_cast<__half2*>(&Asm[row][q * 4]);
            dst[0] = lo;
            dst[1] = hi;
        }
        // ---- load B chunk: 128 j x 64 k fp16 from g_Wh ----
        // 2048 uint2(4 halves) loads? use 8B loads: 8192 halves = 1024 x 8B
#pragma unroll
        for (int it = 0; it < 4; it++) {
            int idx = t + it * 256;          // 0..1023
            int row = idx >> 3;              // /8 -> j
            int q   = idx & 7;               // 8B chunk within 64 k (8 halves each... no, 4)
            // 64 halves per row = 8 chunks of 8 halves (16B)
            const uint4* src = reinterpret_cast<const uint4*>(g_Wh + row * D + kc * KC);
            uint4 v = src[q];
            // dest offset q*8 halves = 16B; row base KPAD*2=144B (16B aligned)
            *reinterpret_cast<uint4*>(&Bsm[row][q * 8]) = v;
        }
        __syncthreads();

        // ---- A fragments for 4 k-steps ----
        uint32_t a[4][4];
#pragma unroll
        for (int ks = 0; ks < 4; ks++) {
            int kk = ks * 16;
            a[ks][0] = *reinterpret_cast<const uint32_t*>(&Asm[mrow][kk + qc]);
            a[ks][1] = *reinterpret_cast<const uint32_t*>(&Asm[mrow + 8][kk + qc]);
            a[ks][2] = *reinterpret_cast<const uint32_t*>(&Asm[mrow][kk + 8 + qc]);
            a[ks][3] = *reinterpret_cast<const uint32_t*>(&Asm[mrow + 8][kk + 8 + qc]);
        }

        // ---- 16 n-tiles x 4 k-steps of mma ----
#pragma unroll
        for (int j = 0; j < 16; j++) {
            int n0 = j * 8;
            const __half* brow = &Bsm[n0 + qr][0];
#pragma unroll
            for (int ks = 0; ks < 4; ks++) {
                int kk = ks * 16;
                uint32_t b0 = *reinterpret_cast<const uint32_t*>(brow + kk + qc);
                uint32_t b1 = *reinterpret_cast<const uint32_t*>(brow + kk + 8 + qc);
                mma16816(acc[j], a[ks][0], a[ks][1], a[ks][2], a[ks][3], b0, b1);
            }
        }
        __syncthreads();
    }

    // ---- epilogue: fp32 acc -> fp16 hW ----
    const int r0 = m0 + mrow;
    const int r1 = r0 + 8;
#pragma unroll
    for (int j = 0; j < 16; j++) {
        int col = j * 8 + qc;
        if (r0 < N)
            *reinterpret_cast<__half2*>(&g_hWh[(size_t)r0 * D + col]) =
                __floats2half2_rn(acc[j].x, acc[j].y);
        if (r1 < N)
            *reinterpret_cast<__half2*>(&g_hWh[(size_t)r1 * D + col]) =
                __floats2half2_rn(acc[j].z, acc[j].w);
    }
}

// ---------------------------------------------------------------------------
// Kernel 2: build CSR row pointers from sorted edge_rows. O(E) scatter.
// ---------------------------------------------------------------------------
__global__ __launch_bounds__(256) void build_rowptr_kernel(
    const int* __restrict__ rows, int E, int N)
{
    int e = blockIdx.x * blockDim.x + threadIdx.x;
    if (e >= E) return;
    int r     = rows[e];
    int rprev = (e == 0) ? -1 : rows[e - 1];
    for (int i = rprev + 1; i <= r; i++) g_rowptr[i] = e;
    if (e == E - 1) {
        for (int i = r + 1; i <= N; i++) g_rowptr[i] = E;
    }
}

// ---------------------------------------------------------------------------
// Kernel 3: SpMM (fp16 gather, fp32 accum) + bias + ReLU. One warp per node.
// Lane l owns dims 4l..4l+3 (8 bytes of fp16 per row).
// ---------------------------------------------------------------------------
__global__ __launch_bounds__(256) void spmm_kernel(
    const int*   __restrict__ cols,
    const float* __restrict__ vals,
    const float* __restrict__ b,
    float*       __restrict__ out,
    int N)
{
    const int warp = (blockIdx.x * blockDim.x + threadIdx.x) >> 5;
    const int lane = threadIdx.x & 31;
    if (warp >= N) return;

    const int lo = g_rowptr[warp];
    const int hi = g_rowptr[warp + 1];

    const uint2* __restrict__ hW8 = reinterpret_cast<const uint2*>(g_hWh);

    float4 acc = make_float4(0.f, 0.f, 0.f, 0.f);

    for (int e0 = lo; e0 < hi; e0 += 32) {
        const int n = min(32, hi - e0);
        int   c = 0;
        float v = 0.f;
        if (lane < n) {
            c = cols[e0 + lane];
            v = vals[e0 + lane];
        }
        int j = 0;
        for (; j + 1 < n; j += 2) {
            int   c0 = __shfl_sync(0xffffffffu, c, j);
            float v0 = __shfl_sync(0xffffffffu, v, j);
            int   c1 = __shfl_sync(0xffffffffu, c, j + 1);
            float v1 = __shfl_sync(0xffffffffu, v, j + 1);
            uint2 r0 = hW8[(size_t)c0 * 32 + lane];
            uint2 r1 = hW8[(size_t)c1 * 32 + lane];
            float2 x0 = __half22float2(*reinterpret_cast<__half2*>(&r0.x));
            float2 y0 = __half22float2(*reinterpret_cast<__half2*>(&r0.y));
            float2 x1 = __half22float2(*reinterpret_cast<__half2*>(&r1.x));
            float2 y1 = __half22float2(*reinterpret_cast<__half2*>(&r1.y));
            acc.x = fmaf(v0, x0.x, acc.x);
            acc.y = fmaf(v0, x0.y, acc.y);
            acc.z = fmaf(v0, y0.x, acc.z);
            acc.w = fmaf(v0, y0.y, acc.w);
            acc.x = fmaf(v1, x1.x, acc.x);
            acc.y = fmaf(v1, x1.y, acc.y);
            acc.z = fmaf(v1, y1.x, acc.z);
            acc.w = fmaf(v1, y1.y, acc.w);
        }
        if (j < n) {
            int   c0 = __shfl_sync(0xffffffffu, c, j);
            float v0 = __shfl_sync(0xffffffffu, v, j);
            uint2 r0 = hW8[(size_t)c0 * 32 + lane];
            float2 x0 = __half22float2(*reinterpret_cast<__half2*>(&r0.x));
            float2 y0 = __half22float2(*reinterpret_cast<__half2*>(&r0.y));
            acc.x = fmaf(v0, x0.x, acc.x);
            acc.y = fmaf(v0, x0.y, acc.y);
            acc.z = fmaf(v0, y0.x, acc.z);
            acc.w = fmaf(v0, y0.y, acc.w);
        }
    }

    const float4 bb = reinterpret_cast<const float4*>(b)[lane];
    float4 o;
    o.x = fmaxf(acc.x + bb.x, 0.f);
    o.y = fmaxf(acc.y + bb.y, 0.f);
    o.z = fmaxf(acc.z + bb.z, 0.f);
    o.w = fmaxf(acc.w + bb.w, 0.f);
    reinterpret_cast<float4*>(out)[(size_t)warp * 32 + lane] = o;
}

// ---------------------------------------------------------------------------
// Inputs (metadata order): edge_rows i32, edge_cols i32, edge_vals f32,
//                          h f32 [N,128], W f32 [128,128], b f32 [128]
// ---------------------------------------------------------------------------
extern "C" void kernel_launch(void* const* d_in, const int* in_sizes, int n_in,
                              void* d_out, int out_size)
{
    const int*   rows = (const int*)  d_in[0];
    const int*   cols = (const int*)  d_in[1];
    const float* vals = (const float*)d_in[2];
    const float* h    = (const float*)d_in[3];
    const float* W    = (const float*)d_in[4];
    const float* b    = (const float*)d_in[5];
    float*       out  = (float*)d_out;

    const int E = in_sizes[0];
    const int N = in_sizes[3] / D;   // 100000

    convert_w_kernel<<<(D * D + 255) / 256, 256>>>(W);
    gemm_hwt_fp16_kernel<<<(N + 127) / 128, 256>>>(h, N);
    build_rowptr_kernel<<<(E + 255) / 256, 256>>>(rows, E, N);
    spmm_kernel<<<(N + 7) / 8, 256>>>(cols, vals, b, out, N);
}